// round 3
// baseline (speedup 1.0000x reference)
#include <cuda_runtime.h>

#define NN 50000
#define EE 800000
#define CIN 256
#define HD  256   // H*D
#define DD  64
#define HH  4

// ---- device scratch (no allocations allowed) ----
__device__ float g_q[(size_t)NN * HD];
__device__ float g_k[(size_t)NN * HD];
__device__ float g_v[(size_t)NN * HD];
__device__ float g_acc[NN * HH];   // unnormalized sum of exp(score) per (dst, head)
__device__ float g_hsum[HH];       // softmax denominator per head

// ---------------------------------------------------------------
// K0: zero accumulators (must run every launch; graph replays reuse scratch)
// ---------------------------------------------------------------
__global__ void init_k() {
    int i = blockIdx.x * blockDim.x + threadIdx.x;
    if (i < NN * HH) g_acc[i] = 0.f;
    if (i < HH)      g_hsum[i] = 0.f;
}

// ---------------------------------------------------------------
// K1: q,k,v = x @ {Wq,Wk,Wv} + bias    (N x 256) @ (256 x 256) x3
// Tiled fp32 GEMM, BM=BN=64, BK=16, 256 threads, 4x4 per thread.
// grid = (12 col-tiles covering 768 cols, ceil(N/64) row-tiles)
// ---------------------------------------------------------------
__global__ __launch_bounds__(256) void gemm_qkv(
    const float* __restrict__ x,
    const float* __restrict__ Wq, const float* __restrict__ bq,
    const float* __restrict__ Wk, const float* __restrict__ bk,
    const float* __restrict__ Wv, const float* __restrict__ bv)
{
    __shared__ float As[16 * 65];   // [kk][m], padded
    __shared__ float Bs[16 * 64];   // [kk][n]

    const int t  = threadIdx.x;
    const int tx = t & 15, ty = t >> 4;
    const int rowBase = blockIdx.y * 64;
    const int colG    = blockIdx.x * 64;
    const int which   = colG >> 8;        // 0:q 1:k 2:v
    const int wcol0   = colG & 255;

    const float* W    = (which == 0) ? Wq : (which == 1) ? Wk : Wv;
    const float* bias = (which == 0) ? bq : (which == 1) ? bk : bv;
    float*       OUT  = (which == 0) ? g_q : (which == 1) ? g_k : g_v;

    float acc[4][4] = {};

    for (int kt = 0; kt < CIN; kt += 16) {
        #pragma unroll
        for (int j = 0; j < 4; j++) {
            int li = t + j * 256;
            int m = li >> 4, kk = li & 15;
            int row = rowBase + m;
            As[kk * 65 + m] = (row < NN) ? x[(size_t)row * CIN + kt + kk] : 0.f;
        }
        #pragma unroll
        for (int j = 0; j < 4; j++) {
            int li = t + j * 256;
            int kk = li >> 6, n = li & 63;
            Bs[kk * 64 + n] = W[(size_t)(kt + kk) * HD + wcol0 + n];
        }
        __syncthreads();

        #pragma unroll
        for (int kk = 0; kk < 16; kk++) {
            float a[4];
            #pragma unroll
            for (int i = 0; i < 4; i++) a[i] = As[kk * 65 + ty * 4 + i];
            float4 b4 = *(const float4*)&Bs[kk * 64 + tx * 4];
            float b[4] = {b4.x, b4.y, b4.z, b4.w};
            #pragma unroll
            for (int i = 0; i < 4; i++)
                #pragma unroll
                for (int jj = 0; jj < 4; jj++)
                    acc[i][jj] += a[i] * b[jj];
        }
        __syncthreads();
    }

    #pragma unroll
    for (int i = 0; i < 4; i++) {
        int row = rowBase + ty * 4 + i;
        if (row >= NN) continue;
        #pragma unroll
        for (int jj = 0; jj < 4; jj++) {
            int c = wcol0 + tx * 4 + jj;
            OUT[(size_t)row * HD + c] = acc[i][jj] + bias[c];
        }
    }
}

// ---------------------------------------------------------------
// K2: per-edge scores -> exp -> scalar scatter-add.
// One warp per edge; lanes [8h .. 8h+7] compute head h's 64-dim dot.
// scores are O(1..4), so exp without max-subtraction is safe; softmax
// normalization happens via g_hsum in K3 (mathematically identical).
// edge_index arrives as int32 (JAX x64 disabled downcasts int64 -> int32).
// ---------------------------------------------------------------
__global__ __launch_bounds__(256) void edge_k(
    const int* __restrict__ ei,
    const float* __restrict__ pos,
    const float* __restrict__ Wg, const float* __restrict__ bg)
{
    __shared__ float bsum[HH];
    const int t = threadIdx.x;
    if (t < HH) bsum[t] = 0.f;
    __syncthreads();

    const int lane = t & 31;
    const int h = lane >> 3, sub = lane & 7;
    const int wpb = blockDim.x >> 5;
    const int warp = t >> 5;

    const float wg0 = Wg[h], wg1 = Wg[4 + h], wg2 = Wg[8 + h], wg3 = Wg[12 + h];
    const float bgh = bg[h];

    float psum = 0.f;

    for (int e = blockIdx.x * wpb + warp; e < EE; e += gridDim.x * wpb) {
        const int src = __ldg(&ei[e]);
        const int dst = __ldg(&ei[EE + e]);

        const float4* qp = (const float4*)(g_q + (size_t)src * HD + h * DD + sub * 8);
        const float4* kp = (const float4*)(g_k + (size_t)dst * HD + h * DD + sub * 8);
        float4 a0 = qp[0], a1 = qp[1];
        float4 b0 = kp[0], b1 = kp[1];

        float d = a0.x * b0.x + a0.y * b0.y + a0.z * b0.z + a0.w * b0.w
                + a1.x * b1.x + a1.y * b1.y + a1.z * b1.z + a1.w * b1.w;
        d += __shfl_xor_sync(0xffffffffu, d, 4);
        d += __shfl_xor_sync(0xffffffffu, d, 2);
        d += __shfl_xor_sync(0xffffffffu, d, 1);

        if (sub == 0) {
            float dx = __ldg(&pos[dst * 3 + 0]) - __ldg(&pos[src * 3 + 0]);
            float dy = __ldg(&pos[dst * 3 + 1]) - __ldg(&pos[src * 3 + 1]);
            float dz = __ldg(&pos[dst * 3 + 2]) - __ldg(&pos[src * 3 + 2]);
            float dist = sqrtf(dx * dx + dy * dy + dz * dz);
            float inv = 1.f / (dist + 1e-8f);
            float gw = bgh + dist * wg0 + dx * inv * wg1 + dy * inv * wg2 + dz * inv * wg3;
            float p = expf(d * 0.125f + gw);
            atomicAdd(&g_acc[dst * HH + h], p);
            psum += p;
        }
    }

    if (sub == 0) atomicAdd(&bsum[h], psum);
    __syncthreads();
    if (t < HH) atomicAdd(&g_hsum[t], bsum[t]);
}

// ---------------------------------------------------------------
// K3: out[n,:] = (acc[n,h]/Z_h * v[n,h,:]).flatten() @ Wo + bo
// 8 nodes per block, thread (node,d); Wo stays hot in L1.
// ---------------------------------------------------------------
__global__ __launch_bounds__(512) void out_k(
    const float* __restrict__ Wo, const float* __restrict__ bo,
    float* __restrict__ out)
{
    __shared__ float s_vw[8 * HD];
    __shared__ float sInv[HH];
    const int t = threadIdx.x;
    if (t < HH) sInv[t] = 1.f / g_hsum[t];
    __syncthreads();

    const int base = blockIdx.x * 8;
    for (int j = t; j < 8 * HD; j += 512) {
        int node = j >> 8;
        int i = j & 255;
        int n = base + node;
        int h = i >> 6;
        s_vw[j] = g_acc[n * HH + h] * sInv[h] * g_v[(size_t)n * HD + i];
    }
    __syncthreads();

    const int node = t >> 6;
    const int d = t & 63;
    const int n = base + node;
    float acc = bo[d];
    const float* vw = &s_vw[node * HD];
    #pragma unroll 8
    for (int i = 0; i < HD; i++)
        acc += vw[i] * Wo[i * DD + d];
    out[(size_t)n * DD + d] = acc;
}

// ---------------------------------------------------------------
extern "C" void kernel_launch(void* const* d_in, const int* in_sizes, int n_in,
                              void* d_out, int out_size)
{
    const float* x   = (const float*)d_in[0];
    const int*   ei  = (const int*)d_in[1];
    const float* pos = (const float*)d_in[2];
    const float* Wq  = (const float*)d_in[3];
    const float* bq  = (const float*)d_in[4];
    const float* Wk  = (const float*)d_in[5];
    const float* bk  = (const float*)d_in[6];
    const float* Wv  = (const float*)d_in[7];
    const float* bv  = (const float*)d_in[8];
    const float* Wg  = (const float*)d_in[9];
    const float* bg  = (const float*)d_in[10];
    const float* Wo  = (const float*)d_in[11];
    const float* bo  = (const float*)d_in[12];
    float*       out = (float*)d_out;

    init_k<<<(NN * HH + 255) / 256, 256>>>();

    dim3 ggrid(12, (NN + 63) / 64);
    gemm_qkv<<<ggrid, 256>>>(x, Wq, bq, Wk, bk, Wv, bv);

    edge_k<<<2048, 256>>>(ei, pos, Wg, bg);

    out_k<<<NN / 8, 512>>>(Wo, bo, out);
}

// round 5
// speedup vs baseline: 2.1366x; 2.1366x over previous
#include <cuda_runtime.h>
#include <cuda_bf16.h>
#include <cstdint>

#define NN 50000
#define EE 800000
#define CIN 256
#define HD  256   // H*D
#define DD  64
#define HH  4

// ---------------- device scratch ----------------
__device__ __nv_bfloat16 g_xhi[(size_t)NN * CIN];
__device__ __nv_bfloat16 g_xlo[(size_t)NN * CIN];
__device__ __nv_bfloat16 g_whi[768 * 256];   // [outcol][k]  (B^T layout: col-major B)
__device__ __nv_bfloat16 g_wlo[768 * 256];
__device__ float g_bvo[256];
__device__ float g_q[(size_t)NN * HD];
__device__ float g_k[(size_t)NN * HD];
__device__ float g_u[(size_t)NN * HD];       // u = x @ (Wv@Wo per head) + bvo
__device__ float g_acc[NN * HH];
__device__ float g_hsum[HH];

// ---------------- K0a: split x into bf16 hi/lo ----------------
__global__ __launch_bounds__(256) void conv_x_k(const float* __restrict__ x) {
    size_t g = (size_t)blockIdx.x * 256 + threadIdx.x;   // float4 index
    float4 v = ((const float4*)x)[g];
    __nv_bfloat16 h0 = __float2bfloat16(v.x), h1 = __float2bfloat16(v.y);
    __nv_bfloat16 h2 = __float2bfloat16(v.z), h3 = __float2bfloat16(v.w);
    float l0 = v.x - __bfloat162float(h0), l1 = v.y - __bfloat162float(h1);
    float l2 = v.z - __bfloat162float(h2), l3 = v.w - __bfloat162float(h3);
    __nv_bfloat162* ph = (__nv_bfloat162*)g_xhi;
    __nv_bfloat162* pl = (__nv_bfloat162*)g_xlo;
    ph[g * 2]     = __nv_bfloat162(h0, h1);
    ph[g * 2 + 1] = __nv_bfloat162(h2, h3);
    pl[g * 2]     = __nv_bfloat162(__float2bfloat16(l0), __float2bfloat16(l1));
    pl[g * 2 + 1] = __nv_bfloat162(__float2bfloat16(l2), __float2bfloat16(l3));
}

// ---------------- K0b: build combined weight [Wq|Wk|Wvo], transposed + split ----------------
__global__ __launch_bounds__(768) void conv_w_k(
    const float* __restrict__ Wq, const float* __restrict__ Wk,
    const float* __restrict__ Wv, const float* __restrict__ Wo,
    const float* __restrict__ bv)
{
    __shared__ float sWv[256];
    const int c = blockIdx.x;          // k index 0..255
    const int t = threadIdx.x;         // output col 0..767
    if (t < 256) sWv[t] = Wv[c * 256 + t];
    __syncthreads();
    float w;
    if (t < 256)       w = Wq[c * 256 + t];
    else if (t < 512)  w = Wk[c * 256 + (t - 256)];
    else {
        int i = t - 512, h = i >> 6, d = i & 63;
        float s = 0.f;
        #pragma unroll 8
        for (int j = 0; j < 64; j++) s += sWv[h * 64 + j] * Wo[(h * 64 + j) * 64 + d];
        w = s;
    }
    __nv_bfloat16 hi = __float2bfloat16(w);
    g_whi[t * 256 + c] = hi;
    g_wlo[t * 256 + c] = __float2bfloat16(w - __bfloat162float(hi));
    if (c == 0 && t >= 512) {
        int i = t - 512, h = i >> 6, d = i & 63;
        float s = 0.f;
        for (int j = 0; j < 64; j++) s += bv[h * 64 + j] * Wo[(h * 64 + j) * 64 + d];
        g_bvo[i] = s;
    }
}

// ---------------- K0c: zero accumulators ----------------
__global__ void init_k() {
    int i = blockIdx.x * blockDim.x + threadIdx.x;
    if (i < NN * HH) g_acc[i] = 0.f;
    if (i < HH)      g_hsum[i] = 0.f;
}

// ---------------- K1: HMMA bf16-split GEMM  [50048 x 256] @ [256 x 768] ----------------
// mma.sync.m16n8k16 (sm_80+ path; tcgen05 unavailable on plain sm_100 target).
// Block 128x128, 8 warps (warp tile 32x64), k-chunk 64, 3 passes (hi*hi, hi*lo, lo*hi).
#define ASTRIDE 72   // 64 + 8 pad: 144B row = 36 banks -> conflict-free frags, 16B aligned

__device__ __forceinline__ void mma_bf16(float* c, const uint32_t* a, const uint32_t* b) {
    asm volatile("mma.sync.aligned.m16n8k16.row.col.f32.bf16.bf16.f32 "
        "{%0,%1,%2,%3}, {%4,%5,%6,%7}, {%8,%9}, {%0,%1,%2,%3};"
        : "+f"(c[0]), "+f"(c[1]), "+f"(c[2]), "+f"(c[3])
        : "r"(a[0]), "r"(a[1]), "r"(a[2]), "r"(a[3]), "r"(b[0]), "r"(b[1]));
}

__global__ __launch_bounds__(256) void gemm_mma(
    const float* __restrict__ bq, const float* __restrict__ bk)
{
    __shared__ __align__(16) __nv_bfloat16 As[128][ASTRIDE];
    __shared__ __align__(16) __nv_bfloat16 Bs[128][ASTRIDE];

    const int t = threadIdx.x, wid = t >> 5, lane = t & 31;
    const int gr = lane >> 2, q4 = lane & 3;
    const int rowBase = blockIdx.y * 128;
    const int col0 = blockIdx.x * 128;
    const int m0 = (wid >> 1) * 32, n0 = (wid & 1) * 64;

    float C[2][8][4] = {};

    #pragma unroll 1
    for (int p = 0; p < 3; p++) {
        const __nv_bfloat16* Asrc = (p == 2) ? g_xlo : g_xhi;
        const __nv_bfloat16* Bsrc = (p == 1) ? g_wlo : g_whi;
        #pragma unroll 1
        for (int kt = 0; kt < 256; kt += 64) {
            __syncthreads();
            #pragma unroll
            for (int i = 0; i < 4; i++) {
                int li = t + i * 256;            // 0..1023
                int row = li >> 3, quad = li & 7;
                int growA = rowBase + row;
                uint4 va = make_uint4(0u, 0u, 0u, 0u);
                if (growA < NN)
                    va = *(const uint4*)(Asrc + (size_t)growA * 256 + kt + quad * 8);
                *(uint4*)&As[row][quad * 8] = va;
                uint4 vb = *(const uint4*)(Bsrc + (size_t)(col0 + row) * 256 + kt + quad * 8);
                *(uint4*)&Bs[row][quad * 8] = vb;
            }
            __syncthreads();

            #pragma unroll
            for (int s = 0; s < 4; s++) {
                const int ks = s * 16;
                uint32_t a[2][4], b[8][2];
                #pragma unroll
                for (int f = 0; f < 2; f++) {
                    int r0 = m0 + f * 16 + gr;
                    a[f][0] = *(const uint32_t*)&As[r0][ks + q4 * 2];
                    a[f][1] = *(const uint32_t*)&As[r0 + 8][ks + q4 * 2];
                    a[f][2] = *(const uint32_t*)&As[r0][ks + q4 * 2 + 8];
                    a[f][3] = *(const uint32_t*)&As[r0 + 8][ks + q4 * 2 + 8];
                }
                #pragma unroll
                for (int g = 0; g < 8; g++) {
                    int nn = n0 + g * 8 + gr;
                    b[g][0] = *(const uint32_t*)&Bs[nn][ks + q4 * 2];
                    b[g][1] = *(const uint32_t*)&Bs[nn][ks + q4 * 2 + 8];
                }
                #pragma unroll
                for (int f = 0; f < 2; f++)
                    #pragma unroll
                    for (int g = 0; g < 8; g++)
                        mma_bf16(C[f][g], a[f], b[g]);
            }
        }
    }

    // epilogue: bias + store fp32
    const int which = col0 >> 8;
    const int wcol0 = col0 & 255;
    const float* bias = (which == 0) ? bq : (which == 1) ? bk : g_bvo;
    float*       OUT  = (which == 0) ? g_q : (which == 1) ? g_k : g_u;

    #pragma unroll
    for (int f = 0; f < 2; f++) {
        int r0 = rowBase + m0 + f * 16 + gr;
        #pragma unroll
        for (int g = 0; g < 8; g++) {
            int c = wcol0 + n0 + g * 8 + q4 * 2;
            float b0 = bias[c], b1 = bias[c + 1];
            if (r0 < NN) {
                float2 v = make_float2(C[f][g][0] + b0, C[f][g][1] + b1);
                *(float2*)&OUT[(size_t)r0 * 256 + c] = v;
            }
            if (r0 + 8 < NN) {
                float2 v = make_float2(C[f][g][2] + b0, C[f][g][3] + b1);
                *(float2*)&OUT[(size_t)(r0 + 8) * 256 + c] = v;
            }
        }
    }
}

// ---------------- K2: per-edge scores -> exp -> scalar scatter-add ----------------
__global__ __launch_bounds__(256) void edge_k(
    const int* __restrict__ ei,
    const float* __restrict__ pos,
    const float* __restrict__ Wg, const float* __restrict__ bg)
{
    __shared__ float bsum[HH];
    const int t = threadIdx.x;
    if (t < HH) bsum[t] = 0.f;
    __syncthreads();

    const int lane = t & 31;
    const int h = lane >> 3, sub = lane & 7;
    const int wpb = blockDim.x >> 5;
    const int warp = t >> 5;

    const float wg0 = Wg[h], wg1 = Wg[4 + h], wg2 = Wg[8 + h], wg3 = Wg[12 + h];
    const float bgh = bg[h];

    float psum = 0.f;

    for (int e = blockIdx.x * wpb + warp; e < EE; e += gridDim.x * wpb) {
        const int src = __ldg(&ei[e]);
        const int dst = __ldg(&ei[EE + e]);

        const float4* qp = (const float4*)(g_q + (size_t)src * HD + h * DD + sub * 8);
        const float4* kp = (const float4*)(g_k + (size_t)dst * HD + h * DD + sub * 8);
        float4 a0 = qp[0], a1 = qp[1];
        float4 b0 = kp[0], b1 = kp[1];

        float d = a0.x * b0.x + a0.y * b0.y + a0.z * b0.z + a0.w * b0.w
                + a1.x * b1.x + a1.y * b1.y + a1.z * b1.z + a1.w * b1.w;
        d += __shfl_xor_sync(0xffffffffu, d, 4);
        d += __shfl_xor_sync(0xffffffffu, d, 2);
        d += __shfl_xor_sync(0xffffffffu, d, 1);

        if (sub == 0) {
            float dx = __ldg(&pos[dst * 3 + 0]) - __ldg(&pos[src * 3 + 0]);
            float dy = __ldg(&pos[dst * 3 + 1]) - __ldg(&pos[src * 3 + 1]);
            float dz = __ldg(&pos[dst * 3 + 2]) - __ldg(&pos[src * 3 + 2]);
            float dist = sqrtf(dx * dx + dy * dy + dz * dz);
            float inv = 1.f / (dist + 1e-8f);
            float gw = bgh + dist * wg0 + dx * inv * wg1 + dy * inv * wg2 + dz * inv * wg3;
            float p = expf(d * 0.125f + gw);
            atomicAdd(&g_acc[dst * HH + h], p);
            psum += p;
        }
    }

    if (sub == 0) atomicAdd(&bsum[h], psum);
    __syncthreads();
    if (t < HH) atomicAdd(&g_hsum[t], bsum[t]);
}

// ---------------- K3: out[n,d] = bo[d] + sum_h coef[n,h] * u[n,h*64+d] ----------------
__global__ __launch_bounds__(256) void out_k(
    const float* __restrict__ bo, float* __restrict__ out)
{
    __shared__ float sInv[HH];
    const int t = threadIdx.x;
    if (t < HH) sInv[t] = 1.f / g_hsum[t];
    __syncthreads();

    const int node = blockIdx.x * 4 + (t >> 6);
    const int d = t & 63;
    const float* u = g_u + (size_t)node * HD;
    float acc = bo[d];
    #pragma unroll
    for (int h = 0; h < HH; h++)
        acc += g_acc[node * HH + h] * sInv[h] * u[h * 64 + d];
    out[(size_t)node * DD + d] = acc;
}

// ---------------------------------------------------------------
extern "C" void kernel_launch(void* const* d_in, const int* in_sizes, int n_in,
                              void* d_out, int out_size)
{
    const float* x   = (const float*)d_in[0];
    const int*   ei  = (const int*)d_in[1];
    const float* pos = (const float*)d_in[2];
    const float* Wq  = (const float*)d_in[3];
    const float* bq  = (const float*)d_in[4];
    const float* Wk  = (const float*)d_in[5];
    const float* bk  = (const float*)d_in[6];
    const float* Wv  = (const float*)d_in[7];
    const float* bv  = (const float*)d_in[8];
    const float* Wg  = (const float*)d_in[9];
    const float* bg  = (const float*)d_in[10];
    const float* Wo  = (const float*)d_in[11];
    const float* bo  = (const float*)d_in[12];
    float*       out = (float*)d_out;

    conv_x_k<<<(NN * CIN / 4) / 256, 256>>>(x);         // 12500 blocks
    conv_w_k<<<256, 768>>>(Wq, Wk, Wv, Wo, bv);
    init_k<<<(NN * HH + 255) / 256, 256>>>();

    dim3 ggrid(6, (NN + 127) / 128);                    // 6 col tiles x 391 row tiles
    gemm_mma<<<ggrid, 256>>>(bq, bk);

    edge_k<<<2048, 256>>>(ei, pos, Wg, bg);

    out_k<<<NN / 4, 256>>>(bo, out);
}

// round 6
// speedup vs baseline: 2.3901x; 1.1187x over previous
#include <cuda_runtime.h>
#include <cuda_bf16.h>
#include <cuda_fp16.h>
#include <cstdint>

#define NN 50000
#define EE 800000
#define CIN 256
#define HD  256   // H*D
#define DD  64
#define HH  4

// ---------------- device scratch ----------------
__device__ __nv_bfloat16 g_xhi[(size_t)NN * CIN];
__device__ __nv_bfloat16 g_xlo[(size_t)NN * CIN];
__device__ __nv_bfloat16 g_whi[768 * 256];   // [outcol][k]  (B^T layout: col-major B)
__device__ __nv_bfloat16 g_wlo[768 * 256];
__device__ float g_bvo[256];
__device__ __half g_qh[(size_t)NN * HD];     // q in fp16 (edge kernel traffic /2)
__device__ __half g_kh[(size_t)NN * HD];     // k in fp16
__device__ float g_u[(size_t)NN * HD];       // u = x @ (Wv@Wo per head) + bvo
__device__ float g_acc[NN * HH];
__device__ float g_hsum[HH];

__device__ __forceinline__ uint32_t smem_u32(const void* p) {
    uint32_t a;
    asm("{ .reg .u64 t; cvta.to.shared.u64 t, %1; cvt.u32.u64 %0, t; }" : "=r"(a) : "l"(p));
    return a;
}
__device__ __forceinline__ void ldmatrix_x4(uint32_t& r0, uint32_t& r1, uint32_t& r2, uint32_t& r3, uint32_t addr) {
    asm volatile("ldmatrix.sync.aligned.m8n8.x4.shared.b16 {%0,%1,%2,%3}, [%4];"
        : "=r"(r0), "=r"(r1), "=r"(r2), "=r"(r3) : "r"(addr));
}

// ---------------- K0a: split x into bf16 hi/lo ----------------
__global__ __launch_bounds__(256) void conv_x_k(const float* __restrict__ x) {
    size_t g = (size_t)blockIdx.x * 256 + threadIdx.x;   // float4 index
    float4 v = ((const float4*)x)[g];
    __nv_bfloat16 h0 = __float2bfloat16(v.x), h1 = __float2bfloat16(v.y);
    __nv_bfloat16 h2 = __float2bfloat16(v.z), h3 = __float2bfloat16(v.w);
    float l0 = v.x - __bfloat162float(h0), l1 = v.y - __bfloat162float(h1);
    float l2 = v.z - __bfloat162float(h2), l3 = v.w - __bfloat162float(h3);
    __nv_bfloat162* ph = (__nv_bfloat162*)g_xhi;
    __nv_bfloat162* pl = (__nv_bfloat162*)g_xlo;
    ph[g * 2]     = __nv_bfloat162(h0, h1);
    ph[g * 2 + 1] = __nv_bfloat162(h2, h3);
    pl[g * 2]     = __nv_bfloat162(__float2bfloat16(l0), __float2bfloat16(l1));
    pl[g * 2 + 1] = __nv_bfloat162(__float2bfloat16(l2), __float2bfloat16(l3));
}

// ---------------- K0b: build combined weight [Wq|Wk|Wvo], transposed + split ----------------
__global__ __launch_bounds__(768) void conv_w_k(
    const float* __restrict__ Wq, const float* __restrict__ Wk,
    const float* __restrict__ Wv, const float* __restrict__ Wo,
    const float* __restrict__ bv)
{
    __shared__ float sWv[256];
    const int c = blockIdx.x;          // k index 0..255
    const int t = threadIdx.x;         // output col 0..767
    if (t < 256) sWv[t] = Wv[c * 256 + t];
    __syncthreads();
    float w;
    if (t < 256)       w = Wq[c * 256 + t];
    else if (t < 512)  w = Wk[c * 256 + (t - 256)];
    else {
        int i = t - 512, h = i >> 6, d = i & 63;
        float s = 0.f;
        #pragma unroll 8
        for (int j = 0; j < 64; j++) s += sWv[h * 64 + j] * Wo[(h * 64 + j) * 64 + d];
        w = s;
    }
    __nv_bfloat16 hi = __float2bfloat16(w);
    g_whi[t * 256 + c] = hi;
    g_wlo[t * 256 + c] = __float2bfloat16(w - __bfloat162float(hi));
    if (c == 0 && t >= 512) {
        int i = t - 512, h = i >> 6, d = i & 63;
        float s = 0.f;
        for (int j = 0; j < 64; j++) s += bv[h * 64 + j] * Wo[(h * 64 + j) * 64 + d];
        g_bvo[i] = s;
    }
}

// ---------------- K0c: zero accumulators ----------------
__global__ void init_k() {
    int i = blockIdx.x * blockDim.x + threadIdx.x;
    if (i < NN * HH) g_acc[i] = 0.f;
    if (i < HH)      g_hsum[i] = 0.f;
}

// ---------------- K1: HMMA bf16-split GEMM  [50048 x 256] @ [256 x 768] ----------------
// mma.sync.m16n8k16 with ldmatrix fragment feeds.
// Block 128x128, 8 warps (warp tile 32x64), k-chunk 64, 3 passes (hi*hi, hi*lo, lo*hi).
#define ASTRIDE 72   // 64 + 8 pad: 144B row -> 8-row ldmatrix tiles hit all 32 banks

__device__ __forceinline__ void mma_bf16(float* c, const uint32_t* a, const uint32_t* b) {
    asm volatile("mma.sync.aligned.m16n8k16.row.col.f32.bf16.bf16.f32 "
        "{%0,%1,%2,%3}, {%4,%5,%6,%7}, {%8,%9}, {%0,%1,%2,%3};"
        : "+f"(c[0]), "+f"(c[1]), "+f"(c[2]), "+f"(c[3])
        : "r"(a[0]), "r"(a[1]), "r"(a[2]), "r"(a[3]), "r"(b[0]), "r"(b[1]));
}

__global__ __launch_bounds__(256) void gemm_mma(
    const float* __restrict__ bq, const float* __restrict__ bk)
{
    __shared__ __align__(16) __nv_bfloat16 As[128][ASTRIDE];
    __shared__ __align__(16) __nv_bfloat16 Bs[128][ASTRIDE];

    const int t = threadIdx.x, wid = t >> 5, lane = t & 31;
    const int gr = lane >> 2, q4 = lane & 3;
    const int rowBase = blockIdx.y * 128;
    const int col0 = blockIdx.x * 128;
    const int m0 = (wid >> 1) * 32, n0 = (wid & 1) * 64;

    // per-lane ldmatrix base addresses (byte offsets; + ks*2 per k-step)
    const uint32_t asBase = smem_u32(As);
    const uint32_t bsBase = smem_u32(Bs);
    const int arow = (lane & 15);
    const int acol = (lane >> 4) * 8;
    const int brow = (lane & 7) + ((lane >> 4) & 1) * 8;
    const int bcol = ((lane >> 3) & 1) * 8;
    uint32_t addrA[2], addrB[4];
    #pragma unroll
    for (int f = 0; f < 2; f++)
        addrA[f] = asBase + (uint32_t)(m0 + f * 16 + arow) * (ASTRIDE * 2) + (uint32_t)acol * 2;
    #pragma unroll
    for (int gp = 0; gp < 4; gp++)
        addrB[gp] = bsBase + (uint32_t)(n0 + gp * 16 + brow) * (ASTRIDE * 2) + (uint32_t)bcol * 2;

    float C[2][8][4] = {};

    #pragma unroll 1
    for (int p = 0; p < 3; p++) {
        const __nv_bfloat16* Asrc = (p == 2) ? g_xlo : g_xhi;
        const __nv_bfloat16* Bsrc = (p == 1) ? g_wlo : g_whi;
        #pragma unroll 1
        for (int kt = 0; kt < 256; kt += 64) {
            __syncthreads();
            #pragma unroll
            for (int i = 0; i < 4; i++) {
                int li = t + i * 256;            // 0..1023
                int row = li >> 3, quad = li & 7;
                int growA = rowBase + row;
                uint4 va = make_uint4(0u, 0u, 0u, 0u);
                if (growA < NN)
                    va = *(const uint4*)(Asrc + (size_t)growA * 256 + kt + quad * 8);
                *(uint4*)&As[row][quad * 8] = va;
                uint4 vb = *(const uint4*)(Bsrc + (size_t)(col0 + row) * 256 + kt + quad * 8);
                *(uint4*)&Bs[row][quad * 8] = vb;
            }
            __syncthreads();

            #pragma unroll
            for (int s = 0; s < 4; s++) {
                const uint32_t ko = (uint32_t)(s * 16) * 2;
                uint32_t a[2][4], b[8][2];
                #pragma unroll
                for (int f = 0; f < 2; f++)
                    ldmatrix_x4(a[f][0], a[f][1], a[f][2], a[f][3], addrA[f] + ko);
                #pragma unroll
                for (int gp = 0; gp < 4; gp++)
                    ldmatrix_x4(b[2 * gp][0], b[2 * gp][1], b[2 * gp + 1][0], b[2 * gp + 1][1],
                                addrB[gp] + ko);
                #pragma unroll
                for (int f = 0; f < 2; f++)
                    #pragma unroll
                    for (int g = 0; g < 8; g++)
                        mma_bf16(C[f][g], a[f], b[g]);
            }
        }
    }

    // epilogue: bias; q,k -> fp16, u -> fp32
    const int which = col0 >> 8;
    const int wcol0 = col0 & 255;

    #pragma unroll
    for (int f = 0; f < 2; f++) {
        int r0 = rowBase + m0 + f * 16 + gr;
        #pragma unroll
        for (int g = 0; g < 8; g++) {
            int c = wcol0 + n0 + g * 8 + q4 * 2;
            if (which < 2) {
                const float* bias = (which == 0) ? bq : bk;
                __half* OUT = (which == 0) ? g_qh : g_kh;
                float b0 = bias[c], b1 = bias[c + 1];
                if (r0 < NN)
                    *(__half2*)&OUT[(size_t)r0 * 256 + c] =
                        __floats2half2_rn(C[f][g][0] + b0, C[f][g][1] + b1);
                if (r0 + 8 < NN)
                    *(__half2*)&OUT[(size_t)(r0 + 8) * 256 + c] =
                        __floats2half2_rn(C[f][g][2] + b0, C[f][g][3] + b1);
            } else {
                float b0 = g_bvo[c], b1 = g_bvo[c + 1];
                if (r0 < NN)
                    *(float2*)&g_u[(size_t)r0 * 256 + c] =
                        make_float2(C[f][g][0] + b0, C[f][g][1] + b1);
                if (r0 + 8 < NN)
                    *(float2*)&g_u[(size_t)(r0 + 8) * 256 + c] =
                        make_float2(C[f][g][2] + b0, C[f][g][3] + b1);
            }
        }
    }
}

// ---------------- K2: per-edge scores -> exp -> scalar scatter-add (fp16 q/k) ----------------
__global__ __launch_bounds__(256) void edge_k(
    const int* __restrict__ ei,
    const float* __restrict__ pos,
    const float* __restrict__ Wg, const float* __restrict__ bg)
{
    __shared__ float bsum[HH];
    const int t = threadIdx.x;
    if (t < HH) bsum[t] = 0.f;
    __syncthreads();

    const int lane = t & 31;
    const int h = lane >> 3, sub = lane & 7;
    const int wpb = blockDim.x >> 5;
    const int warp = t >> 5;

    const float wg0 = Wg[h], wg1 = Wg[4 + h], wg2 = Wg[8 + h], wg3 = Wg[12 + h];
    const float bgh = bg[h];

    float psum = 0.f;

    for (int e = blockIdx.x * wpb + warp; e < EE; e += gridDim.x * wpb) {
        const int src = __ldg(&ei[e]);
        const int dst = __ldg(&ei[EE + e]);

        uint4 qa = *(const uint4*)(g_qh + (size_t)src * HD + h * DD + sub * 8);
        uint4 ka = *(const uint4*)(g_kh + (size_t)dst * HD + h * DD + sub * 8);
        const __half2* hq = (const __half2*)&qa;
        const __half2* hk = (const __half2*)&ka;
        float d = 0.f;
        #pragma unroll
        for (int i = 0; i < 4; i++) {
            float2 fq = __half22float2(hq[i]);
            float2 fk = __half22float2(hk[i]);
            d += fq.x * fk.x + fq.y * fk.y;
        }
        d += __shfl_xor_sync(0xffffffffu, d, 4);
        d += __shfl_xor_sync(0xffffffffu, d, 2);
        d += __shfl_xor_sync(0xffffffffu, d, 1);

        if (sub == 0) {
            float dx = __ldg(&pos[dst * 3 + 0]) - __ldg(&pos[src * 3 + 0]);
            float dy = __ldg(&pos[dst * 3 + 1]) - __ldg(&pos[src * 3 + 1]);
            float dz = __ldg(&pos[dst * 3 + 2]) - __ldg(&pos[src * 3 + 2]);
            float dist = sqrtf(dx * dx + dy * dy + dz * dz);
            float inv = 1.f / (dist + 1e-8f);
            float gw = bgh + dist * wg0 + dx * inv * wg1 + dy * inv * wg2 + dz * inv * wg3;
            float p = expf(d * 0.125f + gw);
            atomicAdd(&g_acc[dst * HH + h], p);
            psum += p;
        }
    }

    if (sub == 0) atomicAdd(&bsum[h], psum);
    __syncthreads();
    if (t < HH) atomicAdd(&g_hsum[t], bsum[t]);
}

// ---------------- K3: out[n,d] = bo[d] + sum_h coef[n,h] * u[n,h*64+d] ----------------
__global__ __launch_bounds__(256) void out_k(
    const float* __restrict__ bo, float* __restrict__ out)
{
    __shared__ float sInv[HH];
    const int t = threadIdx.x;
    if (t < HH) sInv[t] = 1.f / g_hsum[t];
    __syncthreads();

    const int node = blockIdx.x * 4 + (t >> 6);
    const int d = t & 63;
    const float* u = g_u + (size_t)node * HD;
    float acc = bo[d];
    #pragma unroll
    for (int h = 0; h < HH; h++)
        acc += g_acc[node * HH + h] * sInv[h] * u[h * 64 + d];
    out[(size_t)node * DD + d] = acc;
}

// ---------------------------------------------------------------
extern "C" void kernel_launch(void* const* d_in, const int* in_sizes, int n_in,
                              void* d_out, int out_size)
{
    const float* x   = (const float*)d_in[0];
    const int*   ei  = (const int*)d_in[1];
    const float* pos = (const float*)d_in[2];
    const float* Wq  = (const float*)d_in[3];
    const float* bq  = (const float*)d_in[4];
    const float* Wk  = (const float*)d_in[5];
    const float* bk  = (const float*)d_in[6];
    const float* Wv  = (const float*)d_in[7];
    const float* bv  = (const float*)d_in[8];
    const float* Wg  = (const float*)d_in[9];
    const float* bg  = (const float*)d_in[10];
    const float* Wo  = (const float*)d_in[11];
    const float* bo  = (const float*)d_in[12];
    float*       out = (float*)d_out;

    conv_x_k<<<(NN * CIN / 4) / 256, 256>>>(x);
    conv_w_k<<<256, 768>>>(Wq, Wk, Wv, Wo, bv);
    init_k<<<(NN * HH + 255) / 256, 256>>>();

    dim3 ggrid(6, (NN + 127) / 128);
    gemm_mma<<<ggrid, 256>>>(bq, bk);

    edge_k<<<2048, 256>>>(ei, pos, Wg, bg);

    out_k<<<NN / 4, 256>>>(bo, out);
}

// round 10
// speedup vs baseline: 3.2895x; 1.3763x over previous
#include <cuda_runtime.h>
#include <cuda_fp16.h>
#include <cstdint>

#define NN 50000
#define EE 800000
#define CIN 256
#define HD  256   // H*D
#define DD  64
#define HH  4

// ---------------- device scratch ----------------
__device__ __half g_xh[(size_t)NN * CIN];    // x in fp16
__device__ __half g_wh[768 * 256];           // [outcol][k]  (B^T layout), fp16
__device__ float g_bvo[256];
__device__ __half g_qh[(size_t)NN * HD];     // q in fp16
__device__ __half g_kh[(size_t)NN * HD];     // k in fp16
__device__ float g_u[(size_t)NN * HD];       // u = x @ (Wv@Wo per head) + bvo
__device__ float g_acc[NN * HH];
__device__ float g_hsum[HH];

__device__ __forceinline__ uint32_t smem_u32(const void* p) {
    uint32_t a;
    asm("{ .reg .u64 t; cvta.to.shared.u64 t, %1; cvt.u32.u64 %0, t; }" : "=r"(a) : "l"(p));
    return a;
}
__device__ __forceinline__ void ldmatrix_x4(uint32_t& r0, uint32_t& r1, uint32_t& r2, uint32_t& r3, uint32_t addr) {
    asm volatile("ldmatrix.sync.aligned.m8n8.x4.shared.b16 {%0,%1,%2,%3}, [%4];"
        : "=r"(r0), "=r"(r1), "=r"(r2), "=r"(r3) : "r"(addr));
}
__device__ __forceinline__ void cp_async16(uint32_t smem_addr, const void* gptr) {
    asm volatile("cp.async.cg.shared.global [%0], [%1], 16;" :: "r"(smem_addr), "l"(gptr));
}
#define CP_COMMIT() asm volatile("cp.async.commit_group;" ::: "memory")
#define CP_WAIT(n)  asm volatile("cp.async.wait_group %0;" :: "n"(n) : "memory")

// ---------------- K0a: x -> fp16 ----------------
__global__ __launch_bounds__(256) void conv_x_k(const float* __restrict__ x) {
    size_t g = (size_t)blockIdx.x * 256 + threadIdx.x;   // float4 index
    float4 v = ((const float4*)x)[g];
    __half2* ph = (__half2*)g_xh;
    ph[g * 2]     = __floats2half2_rn(v.x, v.y);
    ph[g * 2 + 1] = __floats2half2_rn(v.z, v.w);
}

// ---------------- K0b: combined weight [Wq|Wk|Wvo], transposed, fp16 ----------------
__global__ __launch_bounds__(768) void conv_w_k(
    const float* __restrict__ Wq, const float* __restrict__ Wk,
    const float* __restrict__ Wv, const float* __restrict__ Wo,
    const float* __restrict__ bv)
{
    __shared__ float sWv[256];
    const int c = blockIdx.x;          // k index 0..255
    const int t = threadIdx.x;         // output col 0..767
    if (t < 256) sWv[t] = Wv[c * 256 + t];
    __syncthreads();
    float w;
    if (t < 256)       w = Wq[c * 256 + t];
    else if (t < 512)  w = Wk[c * 256 + (t - 256)];
    else {
        int i = t - 512, h = i >> 6, d = i & 63;
        float s = 0.f;
        #pragma unroll 8
        for (int j = 0; j < 64; j++) s += sWv[h * 64 + j] * Wo[(h * 64 + j) * 64 + d];
        w = s;
    }
    g_wh[t * 256 + c] = __float2half_rn(w);
    if (c == 0 && t >= 512) {
        int i = t - 512, h = i >> 6, d = i & 63;
        float s = 0.f;
        for (int j = 0; j < 64; j++) s += bv[h * 64 + j] * Wo[(h * 64 + j) * 64 + d];
        g_bvo[i] = s;
    }
}

// ---------------- K0c: zero accumulators ----------------
__global__ void init_k() {
    int i = blockIdx.x * blockDim.x + threadIdx.x;
    if (i < NN * HH) g_acc[i] = 0.f;
    if (i < HH)      g_hsum[i] = 0.f;
}

// ---------------- K1: single-pass fp16 HMMA GEMM [50048 x 256] @ [256 x 768] ----------------
// Block 128x128, 8 warps (warp tile 32x64), k-chunk 64 (4 chunks), cp.async double buffer.
// Tiles live in DYNAMIC smem (72 KB > 48 KB static cap).
#define ASTRIDE 72
#define STAGE_ELEMS (128 * ASTRIDE)          // halves per stage
#define STAGE_BYTES (STAGE_ELEMS * 2)
#define SMEM_TOTAL  (4 * STAGE_BYTES)        // A0,A1,B0,B1 = 73728 bytes

__device__ __forceinline__ void mma_fp16(float* c, const uint32_t* a, const uint32_t* b) {
    asm volatile("mma.sync.aligned.m16n8k16.row.col.f32.f16.f16.f32 "
        "{%0,%1,%2,%3}, {%4,%5,%6,%7}, {%8,%9}, {%0,%1,%2,%3};"
        : "+f"(c[0]), "+f"(c[1]), "+f"(c[2]), "+f"(c[3])
        : "r"(a[0]), "r"(a[1]), "r"(a[2]), "r"(a[3]), "r"(b[0]), "r"(b[1]));
}

__global__ __launch_bounds__(256) void gemm_mma(
    const float* __restrict__ bq, const float* __restrict__ bk)
{
    extern __shared__ __align__(16) __half smem[];
    __half* As = smem;                       // [2][STAGE_ELEMS]
    __half* Bs = smem + 2 * STAGE_ELEMS;     // [2][STAGE_ELEMS]

    const int t = threadIdx.x, wid = t >> 5, lane = t & 31;
    const int gr = lane >> 2, q4 = lane & 3;
    const int rowBase = blockIdx.y * 128;
    const int col0 = blockIdx.x * 128;
    const int m0 = (wid >> 1) * 32, n0 = (wid & 1) * 64;

    // load indexing: each thread copies 4 x 16B for A and 4 x 16B for B per chunk
    const int lrow = t >> 1;             // 0..127 (2 threads per row)
    const int lq   = (t & 1) * 4;        // quad 0..3 or 4..7
    const int growA = (rowBase + lrow < NN) ? rowBase + lrow : NN - 1;  // clamp: rows>=NN never stored
    const __half* gA = g_xh + (size_t)growA * 256;
    const __half* gB = g_wh + (size_t)(col0 + lrow) * 256;
    const uint32_t sA = smem_u32(&As[lrow * ASTRIDE + lq * 8]);
    const uint32_t sB = smem_u32(&Bs[lrow * ASTRIDE + lq * 8]);

    // ldmatrix per-lane addresses
    const int arow = (lane & 15);
    const int acol = (lane >> 4) * 8;
    const int brow = (lane & 7) + ((lane >> 4) & 1) * 8;
    const int bcol = ((lane >> 3) & 1) * 8;
    uint32_t addrA[2], addrB[4];
    #pragma unroll
    for (int f = 0; f < 2; f++)
        addrA[f] = smem_u32(&As[(m0 + f * 16 + arow) * ASTRIDE + acol]);
    #pragma unroll
    for (int gp = 0; gp < 4; gp++)
        addrB[gp] = smem_u32(&Bs[(n0 + gp * 16 + brow) * ASTRIDE + bcol]);

    float C[2][8][4] = {};

    // prologue: load chunk 0 into stage 0
    #pragma unroll
    for (int i = 0; i < 4; i++) {
        cp_async16(sA + (uint32_t)i * 16, gA + (lq + i) * 8);
        cp_async16(sB + (uint32_t)i * 16, gB + (lq + i) * 8);
    }
    CP_COMMIT();

    #pragma unroll
    for (int kc = 0; kc < 4; kc++) {
        const uint32_t buf = (kc & 1) ? STAGE_BYTES : 0u;
        if (kc < 3) {
            const uint32_t nbuf = ((kc + 1) & 1) ? STAGE_BYTES : 0u;
            const int kt = (kc + 1) * 64;
            #pragma unroll
            for (int i = 0; i < 4; i++) {
                cp_async16(sA + nbuf + (uint32_t)i * 16, gA + kt + (lq + i) * 8);
                cp_async16(sB + nbuf + (uint32_t)i * 16, gB + kt + (lq + i) * 8);
            }
            CP_COMMIT();
            CP_WAIT(1);
        } else {
            CP_WAIT(0);
        }
        __syncthreads();

        #pragma unroll
        for (int s = 0; s < 4; s++) {
            const uint32_t ko = (uint32_t)(s * 16) * 2 + buf;
            uint32_t a[2][4], b[8][2];
            #pragma unroll
            for (int f = 0; f < 2; f++)
                ldmatrix_x4(a[f][0], a[f][1], a[f][2], a[f][3], addrA[f] + ko);
            #pragma unroll
            for (int gp = 0; gp < 4; gp++)
                ldmatrix_x4(b[2 * gp][0], b[2 * gp][1], b[2 * gp + 1][0], b[2 * gp + 1][1],
                            addrB[gp] + ko);
            #pragma unroll
            for (int f = 0; f < 2; f++)
                #pragma unroll
                for (int g = 0; g < 8; g++)
                    mma_fp16(C[f][g], a[f], b[g]);
        }
        __syncthreads();
    }

    // epilogue: bias; q,k -> fp16, u -> fp32
    const int which = col0 >> 8;
    const int wcol0 = col0 & 255;

    #pragma unroll
    for (int f = 0; f < 2; f++) {
        int r0 = rowBase + m0 + f * 16 + gr;
        #pragma unroll
        for (int g = 0; g < 8; g++) {
            int c = wcol0 + n0 + g * 8 + q4 * 2;
            if (which < 2) {
                const float* bias = (which == 0) ? bq : bk;
                __half* OUT = (which == 0) ? g_qh : g_kh;
                float b0 = bias[c], b1 = bias[c + 1];
                if (r0 < NN)
                    *(__half2*)&OUT[(size_t)r0 * 256 + c] =
                        __floats2half2_rn(C[f][g][0] + b0, C[f][g][1] + b1);
                if (r0 + 8 < NN)
                    *(__half2*)&OUT[(size_t)(r0 + 8) * 256 + c] =
                        __floats2half2_rn(C[f][g][2] + b0, C[f][g][3] + b1);
            } else {
                float b0 = g_bvo[c], b1 = g_bvo[c + 1];
                if (r0 < NN)
                    *(float2*)&g_u[(size_t)r0 * 256 + c] =
                        make_float2(C[f][g][0] + b0, C[f][g][1] + b1);
                if (r0 + 8 < NN)
                    *(float2*)&g_u[(size_t)(r0 + 8) * 256 + c] =
                        make_float2(C[f][g][2] + b0, C[f][g][3] + b1);
            }
        }
    }
}

// ---------------- K2: per-edge scores -> exp -> scalar scatter-add (fp16 q/k) ----------------
__global__ __launch_bounds__(256) void edge_k(
    const int* __restrict__ ei,
    const float* __restrict__ pos,
    const float* __restrict__ Wg, const float* __restrict__ bg)
{
    __shared__ float bsum[HH];
    const int t = threadIdx.x;
    if (t < HH) bsum[t] = 0.f;
    __syncthreads();

    const int lane = t & 31;
    const int h = lane >> 3, sub = lane & 7;
    const int wpb = blockDim.x >> 5;
    const int warp = t >> 5;

    const float wg0 = Wg[h], wg1 = Wg[4 + h], wg2 = Wg[8 + h], wg3 = Wg[12 + h];
    const float bgh = bg[h];

    float psum = 0.f;

    for (int e = blockIdx.x * wpb + warp; e < EE; e += gridDim.x * wpb) {
        const int src = __ldg(&ei[e]);
        const int dst = __ldg(&ei[EE + e]);

        uint4 qa = *(const uint4*)(g_qh + (size_t)src * HD + h * DD + sub * 8);
        uint4 ka = *(const uint4*)(g_kh + (size_t)dst * HD + h * DD + sub * 8);
        const __half2* hq = (const __half2*)&qa;
        const __half2* hk = (const __half2*)&ka;
        float d = 0.f;
        #pragma unroll
        for (int i = 0; i < 4; i++) {
            float2 fq = __half22float2(hq[i]);
            float2 fk = __half22float2(hk[i]);
            d += fq.x * fk.x + fq.y * fk.y;
        }
        d += __shfl_xor_sync(0xffffffffu, d, 4);
        d += __shfl_xor_sync(0xffffffffu, d, 2);
        d += __shfl_xor_sync(0xffffffffu, d, 1);

        if (sub == 0) {
            float dx = __ldg(&pos[dst * 3 + 0]) - __ldg(&pos[src * 3 + 0]);
            float dy = __ldg(&pos[dst * 3 + 1]) - __ldg(&pos[src * 3 + 1]);
            float dz = __ldg(&pos[dst * 3 + 2]) - __ldg(&pos[src * 3 + 2]);
            float dist = sqrtf(dx * dx + dy * dy + dz * dz);
            float inv = 1.f / (dist + 1e-8f);
            float gw = bgh + dist * wg0 + dx * inv * wg1 + dy * inv * wg2 + dz * inv * wg3;
            float p = expf(d * 0.125f + gw);
            atomicAdd(&g_acc[dst * HH + h], p);
            psum += p;
        }
    }

    if (sub == 0) atomicAdd(&bsum[h], psum);
    __syncthreads();
    if (t < HH) atomicAdd(&g_hsum[t], bsum[t]);
}

// ---------------- K3: out[n,d] = bo[d] + sum_h coef[n,h] * u[n,h*64+d] ----------------
__global__ __launch_bounds__(256) void out_k(
    const float* __restrict__ bo, float* __restrict__ out)
{
    __shared__ float sInv[HH];
    const int t = threadIdx.x;
    if (t < HH) sInv[t] = 1.f / g_hsum[t];
    __syncthreads();

    const int node = blockIdx.x * 4 + (t >> 6);
    const int d = t & 63;
    const float* u = g_u + (size_t)node * HD;
    float acc = bo[d];
    #pragma unroll
    for (int h = 0; h < HH; h++)
        acc += g_acc[node * HH + h] * sInv[h] * u[h * 64 + d];
    out[(size_t)node * DD + d] = acc;
}

// ---------------------------------------------------------------
extern "C" void kernel_launch(void* const* d_in, const int* in_sizes, int n_in,
                              void* d_out, int out_size)
{
    const float* x   = (const float*)d_in[0];
    const int*   ei  = (const int*)d_in[1];
    const float* pos = (const float*)d_in[2];
    const float* Wq  = (const float*)d_in[3];
    const float* bq  = (const float*)d_in[4];
    const float* Wk  = (const float*)d_in[5];
    const float* bk  = (const float*)d_in[6];
    const float* Wv  = (const float*)d_in[7];
    const float* bv  = (const float*)d_in[8];
    const float* Wg  = (const float*)d_in[9];
    const float* bg  = (const float*)d_in[10];
    const float* Wo  = (const float*)d_in[11];
    const float* bo  = (const float*)d_in[12];
    float*       out = (float*)d_out;

    // unconditional (no static guards per harness contract); idempotent host attr set
    cudaFuncSetAttribute(gemm_mma, cudaFuncAttributeMaxDynamicSharedMemorySize, SMEM_TOTAL);

    conv_x_k<<<(NN * CIN / 4) / 256, 256>>>(x);
    conv_w_k<<<256, 768>>>(Wq, Wk, Wv, Wo, bv);
    init_k<<<(NN * HH + 255) / 256, 256>>>();

    dim3 ggrid(6, (NN + 127) / 128);
    gemm_mma<<<ggrid, 256, SMEM_TOTAL>>>(bq, bk);

    edge_k<<<2048, 256>>>(ei, pos, Wg, bg);

    out_k<<<NN / 4, 256>>>(bo, out);
}

// round 11
// speedup vs baseline: 3.7347x; 1.1353x over previous
#include <cuda_runtime.h>
#include <cuda_fp16.h>
#include <cstdint>

#define NN 50000
#define EE 800000
#define CIN 256
#define HD  256   // H*D
#define DD  64
#define HH  4

// ---------------- device scratch ----------------
__device__ __half g_xh[(size_t)NN * CIN];    // x in fp16
__device__ __half g_wh[768 * 256];           // [outcol][k]  (B^T layout), fp16
__device__ float g_bvo[256];
__device__ __half g_qh[(size_t)NN * HD];     // q in fp16
__device__ __half g_kh[(size_t)NN * HD];     // k in fp16
__device__ float g_u[(size_t)NN * HD];       // u = x @ (Wv@Wo per head) + bvo
__device__ float g_acc[NN * HH];
__device__ float g_hsum[HH];

__device__ __forceinline__ uint32_t smem_u32(const void* p) {
    uint32_t a;
    asm("{ .reg .u64 t; cvta.to.shared.u64 t, %1; cvt.u32.u64 %0, t; }" : "=r"(a) : "l"(p));
    return a;
}
__device__ __forceinline__ void ldmatrix_x4(uint32_t& r0, uint32_t& r1, uint32_t& r2, uint32_t& r3, uint32_t addr) {
    asm volatile("ldmatrix.sync.aligned.m8n8.x4.shared.b16 {%0,%1,%2,%3}, [%4];"
        : "=r"(r0), "=r"(r1), "=r"(r2), "=r"(r3) : "r"(addr));
}
__device__ __forceinline__ void cp_async16(uint32_t smem_addr, const void* gptr) {
    asm volatile("cp.async.cg.shared.global [%0], [%1], 16;" :: "r"(smem_addr), "l"(gptr));
}
#define CP_COMMIT() asm volatile("cp.async.commit_group;" ::: "memory")
#define CP_WAIT(n)  asm volatile("cp.async.wait_group %0;" :: "n"(n) : "memory")

// ---------------- K0a: x -> fp16 ----------------
__global__ __launch_bounds__(256) void conv_x_k(const float* __restrict__ x) {
    size_t g = (size_t)blockIdx.x * 256 + threadIdx.x;   // float4 index
    float4 v = ((const float4*)x)[g];
    __half2* ph = (__half2*)g_xh;
    ph[g * 2]     = __floats2half2_rn(v.x, v.y);
    ph[g * 2 + 1] = __floats2half2_rn(v.z, v.w);
}

// ---------------- K0b: combined weight [Wq|Wk|Wvo], transposed, fp16 ----------------
__global__ __launch_bounds__(768) void conv_w_k(
    const float* __restrict__ Wq, const float* __restrict__ Wk,
    const float* __restrict__ Wv, const float* __restrict__ Wo,
    const float* __restrict__ bv)
{
    __shared__ float sWv[256];
    const int c = blockIdx.x;          // k index 0..255
    const int t = threadIdx.x;         // output col 0..767
    if (t < 256) sWv[t] = Wv[c * 256 + t];
    __syncthreads();
    float w;
    if (t < 256)       w = Wq[c * 256 + t];
    else if (t < 512)  w = Wk[c * 256 + (t - 256)];
    else {
        int i = t - 512, h = i >> 6, d = i & 63;
        float s = 0.f;
        #pragma unroll 8
        for (int j = 0; j < 64; j++) s += sWv[h * 64 + j] * Wo[(h * 64 + j) * 64 + d];
        w = s;
    }
    g_wh[t * 256 + c] = __float2half_rn(w);
    if (c == 0 && t >= 512) {
        int i = t - 512, h = i >> 6, d = i & 63;
        float s = 0.f;
        for (int j = 0; j < 64; j++) s += bv[h * 64 + j] * Wo[(h * 64 + j) * 64 + d];
        g_bvo[i] = s;
    }
}

// ---------------- K0c: zero accumulators ----------------
__global__ void init_k() {
    int i = blockIdx.x * blockDim.x + threadIdx.x;
    if (i < NN * HH) g_acc[i] = 0.f;
    if (i < HH)      g_hsum[i] = 0.f;
}

// ---------------- K1: single-pass fp16 HMMA GEMM [50048 x 256] @ [256 x 768] ----------------
// Block 128x128, 8 warps (warp tile 32x64), k-chunk 64 (4 chunks), cp.async double buffer.
// XOR-swizzled smem (no padding): stage = 128 rows x 64 halves = 16 KB exact.
// phys(row, unit16) = row*128B + (unit ^ (row&7))*16B  -- conflict-free stores + ldmatrix.
#define STAGE_BYTES 16384
#define SMEM_TOTAL  (4 * STAGE_BYTES)        // A0,A1,B0,B1 = 65536 bytes -> 2 blocks/SM

__device__ __forceinline__ void mma_fp16(float* c, const uint32_t* a, const uint32_t* b) {
    asm volatile("mma.sync.aligned.m16n8k16.row.col.f32.f16.f16.f32 "
        "{%0,%1,%2,%3}, {%4,%5,%6,%7}, {%8,%9}, {%0,%1,%2,%3};"
        : "+f"(c[0]), "+f"(c[1]), "+f"(c[2]), "+f"(c[3])
        : "r"(a[0]), "r"(a[1]), "r"(a[2]), "r"(a[3]), "r"(b[0]), "r"(b[1]));
}

__global__ __launch_bounds__(256, 2) void gemm_mma(
    const float* __restrict__ bq, const float* __restrict__ bk)
{
    extern __shared__ __align__(16) char smem[];
    const uint32_t base = smem_u32(smem);
    const uint32_t aBase = base;                       // stages 0/1 at +0 / +STAGE_BYTES
    const uint32_t bBase = base + 2 * STAGE_BYTES;     // stages 0/1

    const int t = threadIdx.x, wid = t >> 5, lane = t & 31;
    const int gr = lane >> 2, q4 = lane & 3;
    const int rowBase = blockIdx.y * 128;
    const int col0 = blockIdx.x * 128;
    const int m0 = (wid >> 1) * 32, n0 = (wid & 1) * 64;

    // ---- cp.async indexing: thread t copies 4 x 16B for A and for B per chunk
    const int lrow = t >> 1;             // 0..127
    const int lq   = (t & 1) * 4;        // first unit (0 or 4)
    const int xr   = lrow & 7;           // store swizzle
    const int growA = (rowBase + lrow < NN) ? rowBase + lrow : NN - 1;  // clamp; rows>=NN never stored
    const __half* gA = g_xh + (size_t)growA * 256;
    const __half* gB = g_wh + (size_t)(col0 + lrow) * 256;
    const uint32_t sAr = aBase + (uint32_t)lrow * 128;
    const uint32_t sBr = bBase + (uint32_t)lrow * 128;
    uint32_t stU[4];
    #pragma unroll
    for (int i = 0; i < 4; i++) stU[i] = (uint32_t)(((lq + i) ^ xr) << 4);

    // ---- ldmatrix row-base addresses (swizzle unit added per k-step)
    const int arow = (lane & 15);
    const int brow = (lane & 7) + ((lane >> 4) & 1) * 8;
    const uint32_t lx7 = (uint32_t)(lane & 7);
    const uint32_t uAbit = (uint32_t)(lane >> 4);          // A: unit lsb
    const uint32_t uBbit = (uint32_t)((lane >> 3) & 1);    // B: unit lsb
    uint32_t addrA[2], addrB[4];
    #pragma unroll
    for (int f = 0; f < 2; f++)
        addrA[f] = aBase + (uint32_t)(m0 + f * 16 + arow) * 128;
    #pragma unroll
    for (int gp = 0; gp < 4; gp++)
        addrB[gp] = bBase + (uint32_t)(n0 + gp * 16 + brow) * 128;

    float C[2][8][4] = {};

    // prologue: chunk 0 -> stage 0
    #pragma unroll
    for (int i = 0; i < 4; i++) {
        cp_async16(sAr + stU[i], gA + (lq + i) * 8);
        cp_async16(sBr + stU[i], gB + (lq + i) * 8);
    }
    CP_COMMIT();

    #pragma unroll
    for (int kc = 0; kc < 4; kc++) {
        const uint32_t buf = (kc & 1) ? STAGE_BYTES : 0u;
        if (kc < 3) {
            const uint32_t nbuf = ((kc + 1) & 1) ? STAGE_BYTES : 0u;
            const int kt = (kc + 1) * 64;
            #pragma unroll
            for (int i = 0; i < 4; i++) {
                cp_async16(sAr + nbuf + stU[i], gA + kt + (lq + i) * 8);
                cp_async16(sBr + nbuf + stU[i], gB + kt + (lq + i) * 8);
            }
            CP_COMMIT();
            CP_WAIT(1);
        } else {
            CP_WAIT(0);
        }
        __syncthreads();

        #pragma unroll
        for (int s = 0; s < 4; s++) {
            const uint32_t uA = ((((uint32_t)s << 1) | uAbit) ^ lx7) << 4;
            const uint32_t uB = ((((uint32_t)s << 1) | uBbit) ^ lx7) << 4;
            uint32_t a[2][4], b[8][2];
            #pragma unroll
            for (int f = 0; f < 2; f++)
                ldmatrix_x4(a[f][0], a[f][1], a[f][2], a[f][3], addrA[f] + buf + uA);
            #pragma unroll
            for (int gp = 0; gp < 4; gp++)
                ldmatrix_x4(b[2 * gp][0], b[2 * gp][1], b[2 * gp + 1][0], b[2 * gp + 1][1],
                            addrB[gp] + buf + uB);
            #pragma unroll
            for (int f = 0; f < 2; f++)
                #pragma unroll
                for (int g = 0; g < 8; g++)
                    mma_fp16(C[f][g], a[f], b[g]);
        }
        __syncthreads();
    }

    // epilogue: bias; q,k -> fp16, u -> fp32
    const int which = col0 >> 8;
    const int wcol0 = col0 & 255;

    #pragma unroll
    for (int f = 0; f < 2; f++) {
        int r0 = rowBase + m0 + f * 16 + gr;
        #pragma unroll
        for (int g = 0; g < 8; g++) {
            int c = wcol0 + n0 + g * 8 + q4 * 2;
            if (which < 2) {
                const float* bias = (which == 0) ? bq : bk;
                __half* OUT = (which == 0) ? g_qh : g_kh;
                float b0 = bias[c], b1 = bias[c + 1];
                if (r0 < NN)
                    *(__half2*)&OUT[(size_t)r0 * 256 + c] =
                        __floats2half2_rn(C[f][g][0] + b0, C[f][g][1] + b1);
                if (r0 + 8 < NN)
                    *(__half2*)&OUT[(size_t)(r0 + 8) * 256 + c] =
                        __floats2half2_rn(C[f][g][2] + b0, C[f][g][3] + b1);
            } else {
                float b0 = g_bvo[c], b1 = g_bvo[c + 1];
                if (r0 < NN)
                    *(float2*)&g_u[(size_t)r0 * 256 + c] =
                        make_float2(C[f][g][0] + b0, C[f][g][1] + b1);
                if (r0 + 8 < NN)
                    *(float2*)&g_u[(size_t)(r0 + 8) * 256 + c] =
                        make_float2(C[f][g][2] + b0, C[f][g][3] + b1);
            }
        }
    }
}

// ---------------- K2: per-edge scores -> exp -> scalar scatter-add ----------------
// 2 edges per warp iteration: 4 independent 16B gathers in flight -> higher MLP.
__global__ __launch_bounds__(256) void edge_k(
    const int* __restrict__ ei,
    const float* __restrict__ pos,
    const float* __restrict__ Wg, const float* __restrict__ bg)
{
    __shared__ float bsum[HH];
    const int t = threadIdx.x;
    if (t < HH) bsum[t] = 0.f;
    __syncthreads();

    const int lane = t & 31;
    const int h = lane >> 3, sub = lane & 7;
    const int wpb = blockDim.x >> 5;
    const int warp = t >> 5;

    const float wg0 = Wg[h], wg1 = Wg[4 + h], wg2 = Wg[8 + h], wg3 = Wg[12 + h];
    const float bgh = bg[h];

    float psum = 0.f;

    const int stride = gridDim.x * wpb * 2;
    for (int e = (blockIdx.x * wpb + warp) * 2; e < EE; e += stride) {
        // EE even, e even -> e+1 always valid
        const int src0 = __ldg(&ei[e]);
        const int dst0 = __ldg(&ei[EE + e]);
        const int src1 = __ldg(&ei[e + 1]);
        const int dst1 = __ldg(&ei[EE + e + 1]);

        const size_t off = (size_t)(h * DD + sub * 8);
        uint4 qa0 = *(const uint4*)(g_qh + (size_t)src0 * HD + off);
        uint4 ka0 = *(const uint4*)(g_kh + (size_t)dst0 * HD + off);
        uint4 qa1 = *(const uint4*)(g_qh + (size_t)src1 * HD + off);
        uint4 ka1 = *(const uint4*)(g_kh + (size_t)dst1 * HD + off);

        float d0 = 0.f, d1 = 0.f;
        {
            const __half2* hq = (const __half2*)&qa0;
            const __half2* hk = (const __half2*)&ka0;
            #pragma unroll
            for (int i = 0; i < 4; i++) {
                float2 fq = __half22float2(hq[i]);
                float2 fk = __half22float2(hk[i]);
                d0 += fq.x * fk.x + fq.y * fk.y;
            }
        }
        {
            const __half2* hq = (const __half2*)&qa1;
            const __half2* hk = (const __half2*)&ka1;
            #pragma unroll
            for (int i = 0; i < 4; i++) {
                float2 fq = __half22float2(hq[i]);
                float2 fk = __half22float2(hk[i]);
                d1 += fq.x * fk.x + fq.y * fk.y;
            }
        }
        #pragma unroll
        for (int m = 4; m >= 1; m >>= 1) {
            d0 += __shfl_xor_sync(0xffffffffu, d0, m);
            d1 += __shfl_xor_sync(0xffffffffu, d1, m);
        }

        if (sub == 0) {
            float dx0 = __ldg(&pos[dst0 * 3 + 0]) - __ldg(&pos[src0 * 3 + 0]);
            float dy0 = __ldg(&pos[dst0 * 3 + 1]) - __ldg(&pos[src0 * 3 + 1]);
            float dz0 = __ldg(&pos[dst0 * 3 + 2]) - __ldg(&pos[src0 * 3 + 2]);
            float dx1 = __ldg(&pos[dst1 * 3 + 0]) - __ldg(&pos[src1 * 3 + 0]);
            float dy1 = __ldg(&pos[dst1 * 3 + 1]) - __ldg(&pos[src1 * 3 + 1]);
            float dz1 = __ldg(&pos[dst1 * 3 + 2]) - __ldg(&pos[src1 * 3 + 2]);

            float dist0 = sqrtf(dx0 * dx0 + dy0 * dy0 + dz0 * dz0);
            float inv0 = 1.f / (dist0 + 1e-8f);
            float gw0 = bgh + dist0 * wg0 + dx0 * inv0 * wg1 + dy0 * inv0 * wg2 + dz0 * inv0 * wg3;
            float p0 = expf(d0 * 0.125f + gw0);

            float dist1 = sqrtf(dx1 * dx1 + dy1 * dy1 + dz1 * dz1);
            float inv1 = 1.f / (dist1 + 1e-8f);
            float gw1 = bgh + dist1 * wg1 * 0.f + dist1 * wg0 + dx1 * inv1 * wg1 + dy1 * inv1 * wg2 + dz1 * inv1 * wg3;
            float p1 = expf(d1 * 0.125f + gw1);

            atomicAdd(&g_acc[dst0 * HH + h], p0);
            atomicAdd(&g_acc[dst1 * HH + h], p1);
            psum += p0 + p1;
        }
    }

    if (sub == 0) atomicAdd(&bsum[h], psum);
    __syncthreads();
    if (t < HH) atomicAdd(&g_hsum[t], bsum[t]);
}

// ---------------- K3: out[n,d] = bo[d] + sum_h coef[n,h] * u[n,h*64+d] ----------------
__global__ __launch_bounds__(256) void out_k(
    const float* __restrict__ bo, float* __restrict__ out)
{
    __shared__ float sInv[HH];
    const int t = threadIdx.x;
    if (t < HH) sInv[t] = 1.f / g_hsum[t];
    __syncthreads();

    const int node = blockIdx.x * 4 + (t >> 6);
    const int d = t & 63;
    const float* u = g_u + (size_t)node * HD;
    float acc = bo[d];
    #pragma unroll
    for (int h = 0; h < HH; h++)
        acc += g_acc[node * HH + h] * sInv[h] * u[h * 64 + d];
    out[(size_t)node * DD + d] = acc;
}

// ---------------------------------------------------------------
extern "C" void kernel_launch(void* const* d_in, const int* in_sizes, int n_in,
                              void* d_out, int out_size)
{
    const float* x   = (const float*)d_in[0];
    const int*   ei  = (const int*)d_in[1];
    const float* pos = (const float*)d_in[2];
    const float* Wq  = (const float*)d_in[3];
    const float* bq  = (const float*)d_in[4];
    const float* Wk  = (const float*)d_in[5];
    const float* bk  = (const float*)d_in[6];
    const float* Wv  = (const float*)d_in[7];
    const float* bv  = (const float*)d_in[8];
    const float* Wg  = (const float*)d_in[9];
    const float* bg  = (const float*)d_in[10];
    const float* Wo  = (const float*)d_in[11];
    const float* bo  = (const float*)d_in[12];
    float*       out = (float*)d_out;

    cudaFuncSetAttribute(gemm_mma, cudaFuncAttributeMaxDynamicSharedMemorySize, SMEM_TOTAL);

    conv_x_k<<<(NN * CIN / 4) / 256, 256>>>(x);
    conv_w_k<<<256, 768>>>(Wq, Wk, Wv, Wo, bv);
    init_k<<<(NN * HH + 255) / 256, 256>>>();

    dim3 ggrid(6, (NN + 127) / 128);
    gemm_mma<<<ggrid, 256, SMEM_TOTAL>>>(bq, bk);

    edge_k<<<2048, 256>>>(ei, pos, Wg, bg);

    out_k<<<NN / 4, 256>>>(bo, out);
}